// round 13
// baseline (speedup 1.0000x reference)
#include <cuda_runtime.h>
#include <cstdint>

// SigLipLoss: loss = (1/N) * sum_ij softplus(s_ij), sign-flip on diagonal.
// Round 12: int8 mma.sync m16n8k32 (2x MACs/instr vs fp16, exact s32 accum).
// Inputs quantized to s8 at scale 1/24; dequant z = (ln10/576)*idot - 10.
// CTA 128x128, warp 32x64, BK=128 (128B rows, SW128 xor swizzle),
// 3-stage cp.async pipeline, certify-one-ahead barrier, 2 CTAs/SM.

#define NN 8192
#define DD 768
#define BM 128
#define BN 128
#define BK 128
#define NROWT (NN / BM)               // 64
#define NCOLT (NN / BN)               // 64
#define NTILES (NROWT * NCOLT)        // 4096
#define KITERS (DD / BK)              // 6
#define NCTA 296
#define ROWBYTES DD                   // 768 (s8)

#define A_B   (BM * 128)              // 16384
#define STAGE_B ((BM + BN) * 128)     // 32768
#define STAGES 3
#define SMEM_TOTAL (STAGES * STAGE_B + 128)

__device__ __align__(16) signed char g_As8[NN * DD];
__device__ __align__(16) signed char g_Bs8[NN * DD];
__device__ float g_partials8[NTILES * 8];
__device__ unsigned g_done;

__device__ __forceinline__ uint32_t smem_u32(const void* p) {
    uint32_t r;
    asm("{ .reg .u64 t; cvta.to.shared.u64 t, %1; cvt.u32.u64 %0, t; }"
        : "=r"(r) : "l"(p));
    return r;
}
__device__ __forceinline__ void cpa16(uint32_t dst, const void* src) {
    asm volatile("cp.async.cg.shared.global [%0], [%1], 16;"
                 :: "r"(dst), "l"(__cvta_generic_to_global(src)) : "memory");
}
__device__ __forceinline__ void ldm_x4(uint32_t* r, uint32_t addr) {
    asm volatile("ldmatrix.sync.aligned.m8n8.x4.shared.b16 {%0,%1,%2,%3}, [%4];"
                 : "=r"(r[0]), "=r"(r[1]), "=r"(r[2]), "=r"(r[3]) : "r"(addr));
}
__device__ __forceinline__ void mma16832s8(int* c, const uint32_t* a,
                                           const uint32_t* b) {
    asm volatile(
        "mma.sync.aligned.m16n8k32.row.col.s32.s8.s8.s32 "
        "{%0,%1,%2,%3}, {%4,%5,%6,%7}, {%8,%9}, {%0,%1,%2,%3};"
        : "+r"(c[0]), "+r"(c[1]), "+r"(c[2]), "+r"(c[3])
        : "r"(a[0]), "r"(a[1]), "r"(a[2]), "r"(a[3]), "r"(b[0]), "r"(b[1]));
}
__device__ __forceinline__ uint32_t q8pack(float4 f) {
    int v0, v1, v2, v3;
    asm("cvt.rni.sat.s8.f32 %0, %1;" : "=r"(v0) : "f"(f.x * 24.0f));
    asm("cvt.rni.sat.s8.f32 %0, %1;" : "=r"(v1) : "f"(f.y * 24.0f));
    asm("cvt.rni.sat.s8.f32 %0, %1;" : "=r"(v2) : "f"(f.z * 24.0f));
    asm("cvt.rni.sat.s8.f32 %0, %1;" : "=r"(v3) : "f"(f.w * 24.0f));
    return (v0 & 0xffu) | ((v1 & 0xffu) << 8) | ((v2 & 0xffu) << 16)
         | ((uint32_t)v3 << 24);
}

__global__ void convert_kernel(const float* __restrict__ A,
                               const float* __restrict__ B) {
    if (blockIdx.x == 0 && threadIdx.x == 0) g_done = 0;
    const int total4 = NN * DD / 4;
    const int stride = gridDim.x * blockDim.x;
    uint32_t* pa = (uint32_t*)g_As8;
    uint32_t* pb = (uint32_t*)g_Bs8;
    for (int i = blockIdx.x * blockDim.x + threadIdx.x; i < total4; i += stride) {
        pa[i] = q8pack(((const float4*)A)[i]);
        pb[i] = q8pack(((const float4*)B)[i]);
    }
}

__global__ __launch_bounds__(256, 2) void siglip_mma_kernel(float* __restrict__ out) {
    extern __shared__ char smem_raw[];
    __shared__ unsigned s_last;
    uint32_t sbase = smem_u32(smem_raw);
    sbase = (sbase + 127u) & ~127u;

    const int tid  = threadIdx.x;
    const int wid  = tid >> 5;
    const int lane = tid & 31;
    const int warp_m = wid & 3;          // 4 m-groups of 32 rows
    const int warp_n = wid >> 2;         // 2 n-groups of 64 cols
    const int cta = blockIdx.x;

    const int ntiles = (NTILES - cta + NCTA - 1) / NCTA;
    const int C = ntiles * KITERS;

    // ---- producer mapping: 8x 16B per thread per chunk (A:4, B:4) ----
    const int r0 = tid >> 3;             // 0..31
    const int c8 = tid & 7;              // 16B col within 128B row
    const uint32_t colp = (uint32_t)((c8 ^ (r0 & 7)) * 16);
    const uint32_t dstA = r0 * 128 + colp;
    const uint32_t dstB = A_B + r0 * 128 + colp;
    const uint32_t cBo = c8 * 16;

    int pKB = 0, pG = cta, issued = 0;
    const char* bA0 = (const char*)g_As8
        + ((size_t)(pG >> 6) * BM + r0) * ROWBYTES + cBo;
    const char* bB0 = (const char*)g_Bs8
        + ((size_t)(pG & 63) * BN + r0) * ROWBYTES + cBo;

#define ISSUE() do {                                                        \
        const uint32_t stb = sbase + (uint32_t)(issued % 3) * STAGE_B;      \
        _Pragma("unroll")                                                   \
        for (int i = 0; i < 4; ++i)                                         \
            cpa16(stb + dstA + i * 4096,                                    \
                  bA0 + (size_t)i * 32 * ROWBYTES + pKB);                   \
        _Pragma("unroll")                                                   \
        for (int i = 0; i < 4; ++i)                                         \
            cpa16(stb + dstB + i * 4096,                                    \
                  bB0 + (size_t)i * 32 * ROWBYTES + pKB);                   \
        asm volatile("cp.async.commit_group;" ::: "memory");                \
        ++issued;                                                           \
        pKB += 128;                                                         \
        if (pKB == DD) {                                                    \
            pKB = 0; pG += NCTA;                                            \
            if (pG < NTILES) {                                              \
                bA0 = (const char*)g_As8                                    \
                    + ((size_t)(pG >> 6) * BM + r0) * ROWBYTES + cBo;       \
                bB0 = (const char*)g_Bs8                                    \
                    + ((size_t)(pG & 63) * BN + r0) * ROWBYTES + cBo;       \
            }                                                               \
        }                                                                   \
    } while (0)

    // ---- ldmatrix per-lane addresses (SW128 xor, 16B chunk = k16 of s8) ----
    // kstep s covers chunks 2s (k0-15) and 2s+1 (k16-31).
    const int rowA = warp_m * 32 + (lane & 15);
    const uint32_t ra7 = (uint32_t)(rowA & 7);
    const uint32_t ca = (uint32_t)(lane >> 4);          // 0: k_lo, 1: k_hi
    uint32_t aAddr[4];
#pragma unroll
    for (int s = 0; s < 4; ++s)
        aAddr[s] = rowA * 128 + (((2u * s + ca) ^ ra7) * 16);

    const int rowB = warp_n * 64 + (lane & 7) + ((lane >> 4) & 1) * 8;
    const uint32_t rb7 = (uint32_t)(lane & 7);
    const uint32_t cb = (uint32_t)((lane >> 3) & 1);    // 0: k_lo, 1: k_hi
    uint32_t bAddr[4];
#pragma unroll
    for (int s = 0; s < 4; ++s)
        bAddr[s] = A_B + rowB * 128 + (((2u * s + cb) ^ rb7) * 16);

    // ---- prologue: fill 3 stages, certify chunk 0 ----
    ISSUE(); ISSUE(); ISSUE();
    asm volatile("cp.async.wait_group 2;" ::: "memory");
    __syncthreads();

    int ch = 0;
    int g = cta;
#pragma unroll 1
    for (int t = 0; t < ntiles; ++t, g += NCTA) {
        int acc[2][8][4];
#pragma unroll
        for (int mt = 0; mt < 2; ++mt)
#pragma unroll
            for (int nt = 0; nt < 8; ++nt)
#pragma unroll
                for (int v = 0; v < 4; ++v) acc[mt][nt][v] = 0;

#pragma unroll 1
        for (int it = 0; it < KITERS; ++it, ++ch) {
            const uint32_t sS = sbase + (uint32_t)(ch % 3) * STAGE_B;
            uint32_t a[2][4], b[4][4];

            // kstep 0..2: load + MMA
#pragma unroll
            for (int ks = 0; ks < 3; ++ks) {
#pragma unroll
                for (int mt = 0; mt < 2; ++mt)
                    ldm_x4(a[mt], sS + aAddr[ks] + mt * 2048);
#pragma unroll
                for (int np = 0; np < 4; ++np)
                    ldm_x4(b[np], sS + bAddr[ks] + np * 2048);
#pragma unroll
                for (int mt = 0; mt < 2; ++mt)
#pragma unroll
                    for (int nt = 0; nt < 8; ++nt)
                        mma16832s8(acc[mt][nt], a[mt],
                                   &b[nt >> 1][(nt & 1) * 2]);
            }

            // kstep 3: load fragments (they survive the barrier in registers)
#pragma unroll
            for (int mt = 0; mt < 2; ++mt)
                ldm_x4(a[mt], sS + aAddr[3] + mt * 2048);
#pragma unroll
            for (int np = 0; np < 4; ++np)
                ldm_x4(b[np], sS + bAddr[3] + np * 2048);

            // certify chunk ch+1; quiesce readers of stage ch%3; refill it
            if (ch + 3 <= C) asm volatile("cp.async.wait_group 1;" ::: "memory");
            else             asm volatile("cp.async.wait_group 0;" ::: "memory");
            __syncthreads();
            if (issued < C) ISSUE();

            // kstep 3 MMA: pure tensor work flowing out of the barrier
#pragma unroll
            for (int mt = 0; mt < 2; ++mt)
#pragma unroll
                for (int nt = 0; nt < 8; ++nt)
                    mma16832s8(acc[mt][nt], a[mt], &b[nt >> 1][(nt & 1) * 2]);
        }

        // ---- de-synchronized epilogue: dequant + softplus (fp32) ----
        const float KQ = 0.003997543564920218f;   // ln10 / 576
        const float BIAS = -10.0f;
        const int rowBase = (g >> 6) * BM;
        const int colBase = (g & 63) * BN;
        float lsum = 0.0f;
#pragma unroll
        for (int mt = 0; mt < 2; ++mt) {
            const int row0 = rowBase + warp_m * 32 + mt * 16 + (lane >> 2);
#pragma unroll
            for (int ntp = 0; ntp < 4; ++ntp) {
                float prod = 1.0f;
#pragma unroll
                for (int h = 0; h < 2; ++h) {
                    const int nt = ntp * 2 + h;
                    const int col0 = colBase + warp_n * 64 + nt * 8 + (lane & 3) * 2;
#pragma unroll
                    for (int v = 0; v < 4; ++v) {
                        const int row = row0 + (v >> 1) * 8;
                        const int col = col0 + (v & 1);
                        float z = fmaf(__int2float_rn(acc[mt][nt][v]), KQ, BIAS);
                        if (row == col) z = -z;
                        lsum += fmaxf(z, 0.0f);
                        prod *= (1.0f + __expf(-fabsf(z)));
                    }
                }
                lsum += __logf(prod);   // product of 8 factors in (1,2]
            }
        }
#pragma unroll
        for (int off = 16; off > 0; off >>= 1)
            lsum += __shfl_down_sync(0xFFFFFFFFu, lsum, off);
        if (lane == 0) g_partials8[g * 8 + wid] = lsum;
    }
#undef ISSUE

    // ---- last CTA out performs the deterministic finalize ----
    __threadfence();
    __syncthreads();
    if (tid == 0)
        s_last = (atomicAdd(&g_done, 1u) == NCTA - 1) ? 1u : 0u;
    __syncthreads();
    if (s_last) {
        __threadfence();
        double* sd = (double*)smem_raw;    // stage buffers dead
        double s = 0.0;
        for (int i = tid; i < NTILES * 8; i += 256)
            s += (double)g_partials8[i];
        sd[tid] = s;
        __syncthreads();
#pragma unroll
        for (int off = 128; off > 0; off >>= 1) {
            if (tid < off) sd[tid] += sd[tid + off];
            __syncthreads();
        }
        if (tid == 0) out[0] = (float)(sd[0] / (double)NN);
    }
}

extern "C" void kernel_launch(void* const* d_in, const int* in_sizes, int n_in,
                              void* d_out, int out_size) {
    cudaFuncSetAttribute(siglip_mma_kernel,
                         cudaFuncAttributeMaxDynamicSharedMemorySize, SMEM_TOTAL);
    convert_kernel<<<2048, 256>>>((const float*)d_in[0], (const float*)d_in[1]);
    siglip_mma_kernel<<<NCTA, 256, SMEM_TOTAL>>>((float*)d_out);
}

// round 14
// speedup vs baseline: 2.9311x; 2.9311x over previous
#include <cuda_runtime.h>
#include <cuda_fp16.h>
#include <cstdint>

// SigLipLoss: loss = (1/N) * sum_ij softplus(s_ij), sign-flip on diagonal.
// Round 13: fully decoupled mbarrier pipeline (NO __syncthreads in the loop).
// BK=32 / 4 stages; full[s] fed by cp.async.mbarrier.arrive.noinc (count 256),
// empty[s] by lane0-per-warp arrives (count 8). Warps drift up to 4 chunks,
// phase-staggering the SMSP so the tensor pipe never starves in lockstep.
// 128x256 tile, warp 64x64, fp16 mma.sync, 2 CTAs/SM, fp16x2 epilogue.

#define NN 8192
#define DD 768
#define BM 128
#define BN 256
#define BK 32
#define NROWT (NN / BM)               // 64
#define NCOLT (NN / BN)               // 32
#define NTILES (NROWT * NCOLT)        // 2048
#define KITERS (DD / BK)              // 24
#define NCTA 296
#define ROWBYTES (DD * 2)             // 1536

#define A_B   (BM * 64)               // 8192
#define STAGE_B ((BM + BN) * 64)      // 24576
#define STAGES 4
#define SMEM_TOTAL (STAGES * STAGE_B + 128)

__device__ __align__(16) __half g_Ahf[NN * DD];
__device__ __align__(16) __half g_Bhf[NN * DD];
__device__ float g_partials8[NTILES * 8];
__device__ unsigned g_done;

__device__ __forceinline__ uint32_t smem_u32(const void* p) {
    uint32_t r;
    asm("{ .reg .u64 t; cvta.to.shared.u64 t, %1; cvt.u32.u64 %0, t; }"
        : "=r"(r) : "l"(p));
    return r;
}
__device__ __forceinline__ void cpa16(uint32_t dst, const void* src) {
    asm volatile("cp.async.cg.shared.global [%0], [%1], 16;"
                 :: "r"(dst), "l"(__cvta_generic_to_global(src)) : "memory");
}
__device__ __forceinline__ void mbar_init(uint32_t a, uint32_t cnt) {
    asm volatile("mbarrier.init.shared.b64 [%0], %1;" :: "r"(a), "r"(cnt) : "memory");
}
__device__ __forceinline__ void mbar_arrive(uint32_t a) {
    asm volatile("mbarrier.arrive.shared.b64 _, [%0];" :: "r"(a) : "memory");
}
__device__ __forceinline__ void cpasync_arrive(uint32_t a) {
    asm volatile("cp.async.mbarrier.arrive.noinc.shared.b64 [%0];"
                 :: "r"(a) : "memory");
}
__device__ __forceinline__ void mbar_wait(uint32_t a, uint32_t parity) {
    asm volatile(
        "{\n\t.reg .pred P;\n"
        "W_%=:\n\t"
        "mbarrier.try_wait.parity.acquire.cta.shared::cta.b64 P, [%0], %1, 0x989680;\n\t"
        "@P bra.uni D_%=;\n\t"
        "bra.uni W_%=;\n"
        "D_%=:\n\t}"
        :: "r"(a), "r"(parity) : "memory");
}
__device__ __forceinline__ void ldm_x4(uint32_t* r, uint32_t addr) {
    asm volatile("ldmatrix.sync.aligned.m8n8.x4.shared.b16 {%0,%1,%2,%3}, [%4];"
                 : "=r"(r[0]), "=r"(r[1]), "=r"(r[2]), "=r"(r[3]) : "r"(addr));
}
__device__ __forceinline__ void mma16816h(uint32_t* c, const uint32_t* a,
                                          const uint32_t* b) {
    asm volatile(
        "mma.sync.aligned.m16n8k16.row.col.f16.f16.f16.f16 "
        "{%0,%1}, {%2,%3,%4,%5}, {%6,%7}, {%0,%1};"
        : "+r"(c[0]), "+r"(c[1])
        : "r"(a[0]), "r"(a[1]), "r"(a[2]), "r"(a[3]), "r"(b[0]), "r"(b[1]));
}
__device__ __forceinline__ __half2 sp_h2exp2(__half2 x) {
    uint32_t r, xi = *(uint32_t*)&x;
    asm("ex2.approx.f16x2 %0, %1;" : "=r"(r) : "r"(xi));
    return *(__half2*)&r;
}

__global__ void convert_kernel(const float* __restrict__ A,
                               const float* __restrict__ B) {
    if (blockIdx.x == 0 && threadIdx.x == 0) g_done = 0;
    const int total4 = NN * DD / 4;
    const int stride = gridDim.x * blockDim.x;
    __half2* pa = (__half2*)g_Ahf;
    __half2* pb = (__half2*)g_Bhf;
    for (int i = blockIdx.x * blockDim.x + threadIdx.x; i < total4; i += stride) {
        float4 a = ((const float4*)A)[i];
        float4 b = ((const float4*)B)[i];
        pa[2 * i + 0] = __floats2half2_rn(a.x, a.y);
        pa[2 * i + 1] = __floats2half2_rn(a.z, a.w);
        pb[2 * i + 0] = __floats2half2_rn(b.x, b.y);
        pb[2 * i + 1] = __floats2half2_rn(b.z, b.w);
    }
}

__global__ __launch_bounds__(256, 2) void siglip_mma_kernel(float* __restrict__ out) {
    extern __shared__ char smem_raw[];
    __shared__ __align__(8) unsigned long long mbars[8];   // full[0..3], empty[0..3]
    __shared__ unsigned s_last;
    uint32_t sbase = smem_u32(smem_raw);
    sbase = (sbase + 127u) & ~127u;
    const uint32_t mb = smem_u32(mbars);

    const int tid  = threadIdx.x;
    const int wid  = tid >> 5;
    const int lane = tid & 31;
    const int warp_m = wid & 1;          // 2 m-groups of 64 rows
    const int warp_n = wid >> 1;         // 4 n-groups of 64 cols
    const int cta = blockIdx.x;

    if (tid == 0) {
#pragma unroll
        for (int s = 0; s < 4; ++s) {
            mbar_init(mb + s * 8, 256);       // full[s]
            mbar_init(mb + 32 + s * 8, 8);    // empty[s]
        }
    }
    __syncthreads();   // one-time: mbarrier init visible

    const int ntiles = (NTILES - cta + NCTA - 1) / NCTA;
    const int C = ntiles * KITERS;

    // ---- producer mapping: 6x 16B per thread per chunk (A:2, B:4) ----
    const int r0 = tid >> 2;             // 0..63
    const int c4 = tid & 3;
    const uint32_t swz = (uint32_t)((c4 ^ ((r0 >> 1) & 3)) * 16);
    const uint32_t dstA = r0 * 64 + swz;
    const uint32_t dstB = A_B + r0 * 64 + swz;
    const uint32_t cBo = c4 * 16;

    int pKB = 0, pG = cta, issued = 0;
    const char* bA0 = (const char*)g_Ahf
        + ((size_t)(pG >> 5) * BM + r0) * ROWBYTES + cBo;
    const char* bB0 = (const char*)g_Bhf
        + ((size_t)(pG & 31) * BN + r0) * ROWBYTES + cBo;

#define ISSUE() do {                                                       \
        const uint32_t stb = sbase + (uint32_t)(issued & 3) * STAGE_B;     \
        cpa16(stb + dstA,            bA0 + pKB);                           \
        cpa16(stb + dstA + 64 * 64,  bA0 + (size_t)64 * ROWBYTES + pKB);   \
        cpa16(stb + dstB,            bB0 + pKB);                           \
        cpa16(stb + dstB + 64 * 64,  bB0 + (size_t)64  * ROWBYTES + pKB);  \
        cpa16(stb + dstB + 128 * 64, bB0 + (size_t)128 * ROWBYTES + pKB);  \
        cpa16(stb + dstB + 192 * 64, bB0 + (size_t)192 * ROWBYTES + pKB);  \
        cpasync_arrive(mb + (uint32_t)(issued & 3) * 8);                   \
        ++issued;                                                          \
        pKB += 64;                                                         \
        if (pKB == DD * 2) {                                               \
            pKB = 0; pG += NCTA;                                           \
            if (pG < NTILES) {                                             \
                bA0 = (const char*)g_Ahf                                   \
                    + ((size_t)(pG >> 5) * BM + r0) * ROWBYTES + cBo;      \
                bB0 = (const char*)g_Bhf                                   \
                    + ((size_t)(pG & 31) * BN + r0) * ROWBYTES + cBo;      \
            }                                                              \
        }                                                                  \
    } while (0)

    // ---- ldmatrix per-lane addresses (XOR swizzle on 64B rows) ----
    const int rowA = warp_m * 64 + (lane & 15);
    const uint32_t xa = (uint32_t)(((lane & 15) >> 1) & 3);
    const uint32_t ca = (uint32_t)(lane >> 4);
    const uint32_t aBase = rowA * 64;
    const uint32_t swzA0 = ((0 + ca) ^ xa) * 16;   // kk = 0
    const uint32_t swzA1 = ((2 + ca) ^ xa) * 16;   // kk = 1

    const int rowB = warp_n * 64 + (lane & 7) + ((lane >> 4) & 1) * 8;
    const uint32_t xb = (uint32_t)((rowB >> 1) & 3);
    const uint32_t cb = (uint32_t)((lane >> 3) & 1);
    const uint32_t bBase = A_B + rowB * 64;
    const uint32_t swzB0 = ((0 + cb) ^ xb) * 16;
    const uint32_t swzB1 = ((2 + cb) ^ xb) * 16;

    // ---- prologue: produce chunks 0..3 (no empty wait needed) ----
    ISSUE(); ISSUE(); ISSUE(); ISSUE();

    int ch = 0;
    int g = cta;
#pragma unroll 1
    for (int t = 0; t < ntiles; ++t, g += NCTA) {
        uint32_t acc[4][8][2];
#pragma unroll
        for (int mt = 0; mt < 4; ++mt)
#pragma unroll
            for (int nt = 0; nt < 8; ++nt) { acc[mt][nt][0] = 0u; acc[mt][nt][1] = 0u; }

#pragma unroll 1
        for (int it = 0; it < KITERS; ++it, ++ch) {
            const int s = ch & 3;
            const uint32_t par = (uint32_t)((ch >> 2) & 1);
            const uint32_t sS = sbase + (uint32_t)s * STAGE_B;
            uint32_t a[4][4], b[4][4];

            // wait data ready (per-warp; warps drift independently)
            if (lane == 0) mbar_wait(mb + s * 8, par);
            __syncwarp();

            // kk0: load + MMA
#pragma unroll
            for (int mt = 0; mt < 4; ++mt)
                ldm_x4(a[mt], sS + aBase + mt * 1024 + swzA0);
#pragma unroll
            for (int np = 0; np < 4; ++np)
                ldm_x4(b[np], sS + bBase + np * 1024 + swzB0);
#pragma unroll
            for (int mt = 0; mt < 4; ++mt)
#pragma unroll
                for (int nt = 0; nt < 8; ++nt)
                    mma16816h(acc[mt][nt], a[mt], &b[nt >> 1][(nt & 1) * 2]);

            // kk1: load fragments, then release the stage (reads done)
#pragma unroll
            for (int mt = 0; mt < 4; ++mt)
                ldm_x4(a[mt], sS + aBase + mt * 1024 + swzA1);
#pragma unroll
            for (int np = 0; np < 4; ++np)
                ldm_x4(b[np], sS + bBase + np * 1024 + swzB1);
            __syncwarp();
            if (lane == 0) mbar_arrive(mb + 32 + s * 8);   // empty[s]

            // kk1 MMA: runway while other warps catch up / producer refills
#pragma unroll
            for (int mt = 0; mt < 4; ++mt)
#pragma unroll
                for (int nt = 0; nt < 8; ++nt)
                    mma16816h(acc[mt][nt], a[mt], &b[nt >> 1][(nt & 1) * 2]);

            // produce chunk ch+4 into stage s (wait all 8 warps done reading)
            if (issued < C) {
                mbar_wait(mb + 32 + s * 8, par);   // all threads; HW sleep
                ISSUE();
            }
        }

        // ---- de-synchronized epilogue (no barriers) ----
        const float SCALE = 2.302585092994046f, BIAS = -10.0f;
        const __half2 S2  = __floats2half2_rn(SCALE, SCALE);
        const __half2 Bi2 = __floats2half2_rn(BIAS, BIAS);
        const __half2 NL2 = __floats2half2_rn(-1.4426950408889634f,
                                              -1.4426950408889634f);
        const __half2 ONE2 = __floats2half2_rn(1.0f, 1.0f);
        const __half2 ZERO2 = __floats2half2_rn(0.0f, 0.0f);
        float lsum = 0.0f;
#pragma unroll
        for (int mt = 0; mt < 4; ++mt) {
#pragma unroll
            for (int q = 0; q < 4; ++q) {
                __half2 zz[4];
#pragma unroll
                for (int h = 0; h < 2; ++h)
#pragma unroll
                    for (int v = 0; v < 2; ++v)
                        zz[h * 2 + v] = __hfma2(
                            *(const __half2*)&acc[mt][2 * q + h][v], S2, Bi2);
                __half2 s2 = __hadd2(
                    __hadd2(__hmax2(zz[0], ZERO2), __hmax2(zz[1], ZERO2)),
                    __hadd2(__hmax2(zz[2], ZERO2), __hmax2(zz[3], ZERO2)));
                float2 fs = __half22float2(s2);
                lsum += fs.x + fs.y;
                __half2 p2 = __hmul2(
                    __hmul2(__hadd2(sp_h2exp2(__hmul2(__habs2(zz[0]), NL2)), ONE2),
                            __hadd2(sp_h2exp2(__hmul2(__habs2(zz[1]), NL2)), ONE2)),
                    __hmul2(__hadd2(sp_h2exp2(__hmul2(__habs2(zz[2]), NL2)), ONE2),
                            __hadd2(sp_h2exp2(__hmul2(__habs2(zz[3]), NL2)), ONE2)));
                float2 fp = __half22float2(p2);
                lsum += __logf(fp.x * fp.y);
            }
        }
        if ((g >> 6) == (g & 31)) {   // diagonal tile: softplus(-z)=softplus(z)-z
            const int rowOff = ((g >> 5) & 1) * 128;
#pragma unroll
            for (int mt = 0; mt < 4; ++mt) {
                const int row = rowOff + warp_m * 64 + mt * 16 + (lane >> 2);
#pragma unroll
                for (int nt = 0; nt < 8; ++nt) {
                    const int col0 = warp_n * 64 + nt * 8 + (lane & 3) * 2;
#pragma unroll
                    for (int v = 0; v < 2; ++v) {
                        const int r_ = row + v * 8;
                        if (r_ == col0 || r_ == col0 + 1) {
                            float2 f = __half22float2(
                                *(const __half2*)&acc[mt][nt][v]);
                            float zd = (r_ == col0) ? fmaf(f.x, SCALE, BIAS)
                                                    : fmaf(f.y, SCALE, BIAS);
                            lsum -= zd;
                        }
                    }
                }
            }
        }
#pragma unroll
        for (int off = 16; off > 0; off >>= 1)
            lsum += __shfl_down_sync(0xFFFFFFFFu, lsum, off);
        if (lane == 0) g_partials8[g * 8 + wid] = lsum;
    }
#undef ISSUE

    // ---- last CTA out performs the deterministic finalize ----
    __threadfence();
    __syncthreads();
    if (tid == 0)
        s_last = (atomicAdd(&g_done, 1u) == NCTA - 1) ? 1u : 0u;
    __syncthreads();
    if (s_last) {
        __threadfence();
        double* sd = (double*)smem_raw;    // stage buffers dead
        double s = 0.0;
        for (int i = tid; i < NTILES * 8; i += 256)
            s += (double)g_partials8[i];
        sd[tid] = s;
        __syncthreads();
#pragma unroll
        for (int off = 128; off > 0; off >>= 1) {
            if (tid < off) sd[tid] += sd[tid + off];
            __syncthreads();
        }
        if (tid == 0) out[0] = (float)(sd[0] / (double)NN);
    }
}

extern "C" void kernel_launch(void* const* d_in, const int* in_sizes, int n_in,
                              void* d_out, int out_size) {
    cudaFuncSetAttribute(siglip_mma_kernel,
                         cudaFuncAttributeMaxDynamicSharedMemorySize, SMEM_TOTAL);
    convert_kernel<<<2048, 256>>>((const float*)d_in[0], (const float*)d_in[1]);
    siglip_mma_kernel<<<NCTA, 256, SMEM_TOTAL>>>((float*)d_out);
}

// round 15
// speedup vs baseline: 3.0553x; 1.0424x over previous
#include <cuda_runtime.h>
#include <cuda_fp16.h>
#include <cstdint>

// SigLipLoss: loss = (1/N) * sum_ij softplus(s_ij), sign-flip on diagonal.
// Round 14: 3 CTAs/SM (three independent barrier domains per SM) with the
// proven R11 skeleton. Tile 128x128, warp 32x64, BK=64, 2-stage cp.async,
// certify-one-ahead barrier, fp16 mma.sync, fp16x2 epilogue, desync partials.

#define NN 8192
#define DD 768
#define BM 128
#define BN 128
#define BK 64
#define NROWT (NN / BM)               // 64
#define NCOLT (NN / BN)               // 64
#define NTILES (NROWT * NCOLT)        // 4096
#define KITERS (DD / BK)              // 12
#define NCTA 444                      // 3 per SM
#define ROWBYTES (DD * 2)             // 1536

#define A_B   (BM * 128)              // 16384
#define STAGE_B ((BM + BN) * 128)     // 32768
#define SMEM_TOTAL (2 * STAGE_B + 128)

__device__ __align__(16) __half g_Ahf[NN * DD];
__device__ __align__(16) __half g_Bhf[NN * DD];
__device__ float g_partials8[NTILES * 8];
__device__ unsigned g_done;

__device__ __forceinline__ uint32_t smem_u32(const void* p) {
    uint32_t r;
    asm("{ .reg .u64 t; cvta.to.shared.u64 t, %1; cvt.u32.u64 %0, t; }"
        : "=r"(r) : "l"(p));
    return r;
}
__device__ __forceinline__ void cpa16(uint32_t dst, const void* src) {
    asm volatile("cp.async.cg.shared.global [%0], [%1], 16;"
                 :: "r"(dst), "l"(__cvta_generic_to_global(src)) : "memory");
}
__device__ __forceinline__ void ldm_x4(uint32_t* r, uint32_t addr) {
    asm volatile("ldmatrix.sync.aligned.m8n8.x4.shared.b16 {%0,%1,%2,%3}, [%4];"
                 : "=r"(r[0]), "=r"(r[1]), "=r"(r[2]), "=r"(r[3]) : "r"(addr));
}
__device__ __forceinline__ void mma16816h(uint32_t* c, const uint32_t* a,
                                          const uint32_t* b) {
    asm volatile(
        "mma.sync.aligned.m16n8k16.row.col.f16.f16.f16.f16 "
        "{%0,%1}, {%2,%3,%4,%5}, {%6,%7}, {%0,%1};"
        : "+r"(c[0]), "+r"(c[1])
        : "r"(a[0]), "r"(a[1]), "r"(a[2]), "r"(a[3]), "r"(b[0]), "r"(b[1]));
}
__device__ __forceinline__ __half2 sp_h2exp2(__half2 x) {
    uint32_t r, xi = *(uint32_t*)&x;
    asm("ex2.approx.f16x2 %0, %1;" : "=r"(r) : "r"(xi));
    return *(__half2*)&r;
}

__global__ void convert_kernel(const float* __restrict__ A,
                               const float* __restrict__ B) {
    if (blockIdx.x == 0 && threadIdx.x == 0) g_done = 0;
    const int total4 = NN * DD / 4;
    const int stride = gridDim.x * blockDim.x;
    __half2* pa = (__half2*)g_Ahf;
    __half2* pb = (__half2*)g_Bhf;
    for (int i = blockIdx.x * blockDim.x + threadIdx.x; i < total4; i += stride) {
        float4 a = ((const float4*)A)[i];
        float4 b = ((const float4*)B)[i];
        pa[2 * i + 0] = __floats2half2_rn(a.x, a.y);
        pa[2 * i + 1] = __floats2half2_rn(a.z, a.w);
        pb[2 * i + 0] = __floats2half2_rn(b.x, b.y);
        pb[2 * i + 1] = __floats2half2_rn(b.z, b.w);
    }
}

__global__ __launch_bounds__(256, 3) void siglip_mma_kernel(float* __restrict__ out) {
    extern __shared__ char smem_raw[];
    __shared__ unsigned s_last;
    uint32_t sbase = smem_u32(smem_raw);
    sbase = (sbase + 127u) & ~127u;

    const int tid  = threadIdx.x;
    const int wid  = tid >> 5;
    const int lane = tid & 31;
    const int warp_m = wid & 3;          // 4 m-groups of 32 rows
    const int warp_n = wid >> 2;         // 2 n-groups of 64 cols
    const int cta = blockIdx.x;

    const int ntiles = (NTILES - cta + NCTA - 1) / NCTA;
    const int C = ntiles * KITERS;

    // ---- producer mapping: 8x 16B per thread per chunk (A:4, B:4) ----
    const int r0 = tid >> 3;             // 0..31
    const int c8 = tid & 7;              // 16B col within 128B row
    const uint32_t colp = (uint32_t)((c8 ^ (r0 & 7)) * 16);
    const uint32_t dstA = r0 * 128 + colp;
    const uint32_t dstB = A_B + r0 * 128 + colp;
    const uint32_t cBo = c8 * 16;

    int pKB = 0, pG = cta, issued = 0;
    const char* bA0 = (const char*)g_Ahf
        + ((size_t)(pG >> 6) * BM + r0) * ROWBYTES + cBo;
    const char* bB0 = (const char*)g_Bhf
        + ((size_t)(pG & 63) * BN + r0) * ROWBYTES + cBo;

#define ISSUE() do {                                                        \
        const uint32_t stb = sbase + (uint32_t)(issued & 1) * STAGE_B;      \
        _Pragma("unroll")                                                   \
        for (int i = 0; i < 4; ++i)                                         \
            cpa16(stb + dstA + i * 4096,                                    \
                  bA0 + (size_t)i * 32 * ROWBYTES + pKB);                   \
        _Pragma("unroll")                                                   \
        for (int i = 0; i < 4; ++i)                                         \
            cpa16(stb + dstB + i * 4096,                                    \
                  bB0 + (size_t)i * 32 * ROWBYTES + pKB);                   \
        asm volatile("cp.async.commit_group;" ::: "memory");                \
        ++issued;                                                           \
        pKB += 128;                                                         \
        if (pKB == DD * 2) {                                                \
            pKB = 0; pG += NCTA;                                            \
            if (pG < NTILES) {                                              \
                bA0 = (const char*)g_Ahf                                    \
                    + ((size_t)(pG >> 6) * BM + r0) * ROWBYTES + cBo;       \
                bB0 = (const char*)g_Bhf                                    \
                    + ((size_t)(pG & 63) * BN + r0) * ROWBYTES + cBo;       \
            }                                                               \
        }                                                                   \
    } while (0)

    // ---- ldmatrix per-lane addresses (SW128 xor on 128B rows) ----
    const int rowA = warp_m * 32 + (lane & 15);
    const uint32_t ra7 = (uint32_t)(rowA & 7);
    const uint32_t ca = (uint32_t)(lane >> 4);
    uint32_t aAddr[4];
#pragma unroll
    for (int kk = 0; kk < 4; ++kk)
        aAddr[kk] = rowA * 128 + (((2u * kk + ca) ^ ra7) * 16);

    const int rowB = warp_n * 64 + (lane & 7) + ((lane >> 4) & 1) * 8;
    const uint32_t rb7 = (uint32_t)(rowB & 7);
    const uint32_t cb = (uint32_t)((lane >> 3) & 1);
    uint32_t bAddr[4];
#pragma unroll
    for (int kk = 0; kk < 4; ++kk)
        bAddr[kk] = A_B + rowB * 128 + (((2u * kk + cb) ^ rb7) * 16);

    // ---- prologue: fill both stages, certify chunk 0 ----
    ISSUE(); ISSUE();
    asm volatile("cp.async.wait_group 1;" ::: "memory");
    __syncthreads();

    int ch = 0;
    int g = cta;
#pragma unroll 1
    for (int t = 0; t < ntiles; ++t, g += NCTA) {
        uint32_t acc[2][8][2];
#pragma unroll
        for (int mt = 0; mt < 2; ++mt)
#pragma unroll
            for (int nt = 0; nt < 8; ++nt) { acc[mt][nt][0] = 0u; acc[mt][nt][1] = 0u; }

#pragma unroll 1
        for (int it = 0; it < KITERS; ++it, ++ch) {
            const uint32_t sS = sbase + (uint32_t)(ch & 1) * STAGE_B;
            uint32_t a[2][4], b[4][4];

            // kk = 0..2: load + MMA
#pragma unroll
            for (int kk = 0; kk < 3; ++kk) {
#pragma unroll
                for (int mt = 0; mt < 2; ++mt)
                    ldm_x4(a[mt], sS + aAddr[kk] + mt * 2048);
#pragma unroll
                for (int np = 0; np < 4; ++np)
                    ldm_x4(b[np], sS + bAddr[kk] + np * 2048);
#pragma unroll
                for (int mt = 0; mt < 2; ++mt)
#pragma unroll
                    for (int nt = 0; nt < 8; ++nt)
                        mma16816h(acc[mt][nt], a[mt], &b[nt >> 1][(nt & 1) * 2]);
            }

            // kk = 3: load fragments (they survive the barrier in registers)
#pragma unroll
            for (int mt = 0; mt < 2; ++mt)
                ldm_x4(a[mt], sS + aAddr[3] + mt * 2048);
#pragma unroll
            for (int np = 0; np < 4; ++np)
                ldm_x4(b[np], sS + bAddr[3] + np * 2048);

            // certify chunk ch+1; quiesce readers of stage ch&1; refill it
            asm volatile("cp.async.wait_group 0;" ::: "memory");
            __syncthreads();
            if (issued < C) ISSUE();

            // kk = 3 MMA: pure tensor work flowing out of the barrier
#pragma unroll
            for (int mt = 0; mt < 2; ++mt)
#pragma unroll
                for (int nt = 0; nt < 8; ++nt)
                    mma16816h(acc[mt][nt], a[mt], &b[nt >> 1][(nt & 1) * 2]);
        }

        // ---- de-synchronized epilogue (no barriers) ----
        const float SCALE = 2.302585092994046f, BIAS = -10.0f;
        const __half2 S2  = __floats2half2_rn(SCALE, SCALE);
        const __half2 Bi2 = __floats2half2_rn(BIAS, BIAS);
        const __half2 NL2 = __floats2half2_rn(-1.4426950408889634f,
                                              -1.4426950408889634f);
        const __half2 ONE2 = __floats2half2_rn(1.0f, 1.0f);
        const __half2 ZERO2 = __floats2half2_rn(0.0f, 0.0f);
        float lsum = 0.0f;
#pragma unroll
        for (int mt = 0; mt < 2; ++mt) {
#pragma unroll
            for (int q = 0; q < 4; ++q) {
                __half2 zz[4];
#pragma unroll
                for (int h = 0; h < 2; ++h)
#pragma unroll
                    for (int v = 0; v < 2; ++v)
                        zz[h * 2 + v] = __hfma2(
                            *(const __half2*)&acc[mt][2 * q + h][v], S2, Bi2);
                __half2 s2 = __hadd2(
                    __hadd2(__hmax2(zz[0], ZERO2), __hmax2(zz[1], ZERO2)),
                    __hadd2(__hmax2(zz[2], ZERO2), __hmax2(zz[3], ZERO2)));
                float2 fs = __half22float2(s2);
                lsum += fs.x + fs.y;
                __half2 p2 = __hmul2(
                    __hmul2(__hadd2(sp_h2exp2(__hmul2(__habs2(zz[0]), NL2)), ONE2),
                            __hadd2(sp_h2exp2(__hmul2(__habs2(zz[1]), NL2)), ONE2)),
                    __hmul2(__hadd2(sp_h2exp2(__hmul2(__habs2(zz[2]), NL2)), ONE2),
                            __hadd2(sp_h2exp2(__hmul2(__habs2(zz[3]), NL2)), ONE2)));
                float2 fp = __half22float2(p2);
                lsum += __logf(fp.x * fp.y);
            }
        }
        if ((g >> 6) == (g & 63)) {   // diagonal tile: softplus(-z)=softplus(z)-z
#pragma unroll
            for (int mt = 0; mt < 2; ++mt) {
                const int row = warp_m * 32 + mt * 16 + (lane >> 2);
#pragma unroll
                for (int nt = 0; nt < 8; ++nt) {
                    const int col0 = warp_n * 64 + nt * 8 + (lane & 3) * 2;
#pragma unroll
                    for (int v = 0; v < 2; ++v) {
                        const int r_ = row + v * 8;
                        if (r_ == col0 || r_ == col0 + 1) {
                            float2 f = __half22float2(
                                *(const __half2*)&acc[mt][nt][v]);
                            float zd = (r_ == col0) ? fmaf(f.x, SCALE, BIAS)
                                                    : fmaf(f.y, SCALE, BIAS);
                            lsum -= zd;
                        }
                    }
                }
            }
        }
#pragma unroll
        for (int off = 16; off > 0; off >>= 1)
            lsum += __shfl_down_sync(0xFFFFFFFFu, lsum, off);
        if (lane == 0) g_partials8[g * 8 + wid] = lsum;
    }
#undef ISSUE

    // ---- last CTA out performs the deterministic finalize ----
    __threadfence();
    __syncthreads();
    if (tid == 0)
        s_last = (atomicAdd(&g_done, 1u) == NCTA - 1) ? 1u : 0u;
    __syncthreads();
    if (s_last) {
        __threadfence();
        double* sd = (double*)smem_raw;    // stage buffers dead
        double s = 0.0;
        for (int i = tid; i < NTILES * 8; i += 256)
            s += (double)g_partials8[i];
        sd[tid] = s;
        __syncthreads();
#pragma unroll
        for (int off = 128; off > 0; off >>= 1) {
            if (tid < off) sd[tid] += sd[tid + off];
            __syncthreads();
        }
        if (tid == 0) out[0] = (float)(sd[0] / (double)NN);
    }
}

extern "C" void kernel_launch(void* const* d_in, const int* in_sizes, int n_in,
                              void* d_out, int out_size) {
    cudaFuncSetAttribute(siglip_mma_kernel,
                         cudaFuncAttributeMaxDynamicSharedMemorySize, SMEM_TOTAL);
    convert_kernel<<<2048, 256>>>((const float*)d_in[0], (const float*)d_in[1]);
    siglip_mma_kernel<<<NCTA, 256, SMEM_TOTAL>>>((float*)d_out);
}